// round 3
// baseline (speedup 1.0000x reference)
#include <cuda_runtime.h>
#include <cstdint>

// Embedding gather, token-clustered:
//   x : [16384] int32 token ids        (d_in[0])
//   W : [1024, 50257] f32 row-major    (d_in[1]); embedding of tok = column tok
//   out[s, :] = W[:, x[s]]
//
// Pipeline:
//   1) counting-sort (tok,pos) pairs by sector group (tok>>3, 6283 buckets)
//   2) gather: warp lanes = 32 consecutive SORTED tokens -> adjacent lanes
//      read adjacent W positions, so the L1 coalescer merges ~32 sector
//      requests into ~13. smem tile transposes for coalesced float4 writes.

#define TOKENS  50257
#define DIMS    1024
#define NTOK    16384
#define NGROUPS ((TOKENS + 7) / 8)     // 6283 sector groups

__device__ int  g_cnt[NGROUPS];        // histogram -> exclusive offsets
__device__ int2 g_sorted[NTOK];        // (tok, original position)

// ---------- sort pipeline ----------

__global__ void k_zero()
{
    int i = blockIdx.x * blockDim.x + threadIdx.x;
    if (i < NGROUPS) g_cnt[i] = 0;
}

__global__ void k_hist(const int* __restrict__ x)
{
    int i = blockIdx.x * blockDim.x + threadIdx.x;
    if (i < NTOK) atomicAdd(&g_cnt[__ldg(&x[i]) >> 3], 1);
}

__global__ __launch_bounds__(1024, 1)
void k_scan()   // single block exclusive scan over NGROUPS counters
{
    __shared__ int buf[1024];
    __shared__ int carry;
    int tid = threadIdx.x;
    if (tid == 0) carry = 0;
    __syncthreads();

    for (int base = 0; base < NGROUPS; base += 1024) {
        int v = (base + tid < NGROUPS) ? g_cnt[base + tid] : 0;
        buf[tid] = v;
        __syncthreads();
        // Hillis-Steele inclusive scan
        for (int off = 1; off < 1024; off <<= 1) {
            int t = (tid >= off) ? buf[tid - off] : 0;
            __syncthreads();
            buf[tid] += t;
            __syncthreads();
        }
        int incl = buf[tid];
        int c = carry;
        __syncthreads();
        if (base + tid < NGROUPS) g_cnt[base + tid] = incl - v + c;
        if (tid == 1023) carry = c + incl;
        __syncthreads();
    }
}

__global__ void k_scatter(const int* __restrict__ x)
{
    int i = blockIdx.x * blockDim.x + threadIdx.x;
    if (i < NTOK) {
        int tok = __ldg(&x[i]);
        int p = atomicAdd(&g_cnt[tok >> 3], 1);
        g_sorted[p] = make_int2(tok, i);
    }
}

// ---------- gather ----------
// grid.x = NTOK/32 token tiles, grid.y = 4 dim chunks of 256.
// 256 threads: phase 1 loads W[dim, tok] with lanes = sorted tokens,
// phase 2 writes coalesced float4 rows via smem transpose.

#define TOK_TILE 32
#define DIM_CHUNK 256

__global__ __launch_bounds__(256)
void k_gather(const float* __restrict__ W, float4* __restrict__ out)
{
    __shared__ float tile[DIM_CHUNK][TOK_TILE + 1];  // +1 pad: conflict-free
    __shared__ int s_tok[TOK_TILE], s_pos[TOK_TILE];

    const int tid = threadIdx.x;
    if (tid < TOK_TILE) {
        int2 e = g_sorted[blockIdx.x * TOK_TILE + tid];
        s_tok[tid] = e.x;
        s_pos[tid] = e.y;
    }
    __syncthreads();

    // Phase 1: each warp covers 32 dims; lanes = clustered tokens.
    const int lane = tid & 31;
    const int wd   = (tid >> 5) * 32;                 // warp's dim base in chunk
    const int tok  = s_tok[lane];
    const float* base = W + (size_t)(blockIdx.y * DIM_CHUNK + wd) * TOKENS + tok;

#pragma unroll
    for (int k = 0; k < 32; k++) {
        tile[wd + k][lane] = __ldg(base + (size_t)k * TOKENS);
    }
    __syncthreads();

    // Phase 2: coalesced float4 stores. tid -> token j = tid>>3, f4 lanes.
    const int j = tid >> 3;
    const int f0 = tid & 7;
    const size_t orow = (size_t)s_pos[j] * (DIMS / 4) + blockIdx.y * (DIM_CHUNK / 4);

#pragma unroll
    for (int k = 0; k < 8; k++) {
        int f4i = f0 + k * 8;
        int d = f4i * 4;
        float4 v = make_float4(tile[d][j], tile[d + 1][j],
                               tile[d + 2][j], tile[d + 3][j]);
        __stwt(&out[orow + f4i], v);
    }
}

// ---------- launch ----------

extern "C" void kernel_launch(void* const* d_in, const int* in_sizes, int n_in,
                              void* d_out, int out_size)
{
    const int*   x = (const int*)  d_in[0];
    const float* W = (const float*)d_in[1];
    float4*      o = (float4*)     d_out;

    k_zero   <<<(NGROUPS + 255) / 256, 256>>>();
    k_hist   <<<(NTOK    + 255) / 256, 256>>>(x);
    k_scan   <<<1, 1024>>>();
    k_scatter<<<(NTOK    + 255) / 256, 256>>>(x);

    dim3 grid(NTOK / TOK_TILE, DIMS / DIM_CHUNK);   // (512, 4)
    k_gather <<<grid, 256>>>(W, o);
}

// round 4
// speedup vs baseline: 1.3918x; 1.3918x over previous
#include <cuda_runtime.h>
#include <cstdint>

// Embedding gather, bucket-clustered (no sort):
//   x : [16384] int32 token ids        (d_in[0])
//   W : [1024, 50257] f32 row-major    (d_in[1]); embedding of tok = column tok
//   out[s, :] = W[:, x[s]]
//
// 1) bin tokens into 786 buckets of 64 consecutive ids (256B = 8 sectors)
//    via atomic append — order within bucket irrelevant, coalescer merges
//    by sector.
// 2) gather: block = (bucket, 256-dim chunk); warp lanes = bucket entries,
//    so each warp-LDG touches <= 8 sectors (vs 32 unclustered). smem
//    transpose yields coalesced 128B-line float4 stores.

#define TOKENS   50257
#define DIMS     1024
#define NTOK     16384
#define BSHIFT   6
#define NBUCKETS ((TOKENS + 63) / 64)   // 786
#define CAP      256                    // mean fill ~20.8; overflow ~impossible

__device__ int  g_cnt[NBUCKETS];
__device__ int2 g_items[NBUCKETS * CAP];   // (tok, original position)

__global__ void k_zero()
{
    int i = blockIdx.x * blockDim.x + threadIdx.x;
    if (i < NBUCKETS) g_cnt[i] = 0;
}

__global__ void k_bin(const int* __restrict__ x)
{
    int i = blockIdx.x * blockDim.x + threadIdx.x;
    if (i < NTOK) {
        int tok = __ldg(&x[i]);
        int b   = tok >> BSHIFT;
        int s   = atomicAdd(&g_cnt[b], 1);
        if (s < CAP) g_items[b * CAP + s] = make_int2(tok, i);
    }
}

// grid (786, 4), 256 threads. Chunk = 256 dims; warp w covers dims
// [w*32, w*32+32); lanes = up to 32 tokens from the bucket.
#define DIM_CHUNK 256

__global__ __launch_bounds__(256)
void k_gather(const float* __restrict__ W, float4* __restrict__ out)
{
    __shared__ float tile[DIM_CHUNK][33];      // [dim][token], pad: bank-free
    __shared__ int s_tok[32], s_pos[32];
    __shared__ int s_n;

    const int b   = blockIdx.x;
    const int tid = threadIdx.x;
    if (tid == 0) s_n = min(g_cnt[b], CAP);
    __syncthreads();
    const int n = s_n;

    const int lane = tid & 31;
    const int wd   = (tid >> 5) * 32;          // warp's dim base within chunk
    const size_t dim_base = (size_t)(blockIdx.y * DIM_CHUNK + wd) * TOKENS;

    for (int t0 = 0; t0 < n; t0 += 32) {
        const int m = min(32, n - t0);

        if (tid < 32 && tid < m) {
            int2 e = g_items[b * CAP + t0 + tid];
            s_tok[tid] = e.x;
            s_pos[tid] = e.y;
        }
        __syncthreads();

        // Phase 1: lanes = clustered tokens (span <= 256B -> <= 8 sectors).
        if (lane < m) {
            const float* base = W + dim_base + s_tok[lane];
#pragma unroll
            for (int k = 0; k < 32; k++)
                tile[wd + k][lane] = __ldg(base + (size_t)k * TOKENS);
        }
        __syncthreads();

        // Phase 2: coalesced stores. j = token slot, 8 float4 per thread;
        // per STG the warp writes 4 x 128B contiguous line segments.
        const int j  = tid >> 3;
        const int f0 = tid & 7;
        if (j < m) {
            const size_t orow = (size_t)s_pos[j] * (DIMS / 4)
                              + blockIdx.y * (DIM_CHUNK / 4);
#pragma unroll
            for (int k = 0; k < 8; k++) {
                int f4i = f0 + k * 8;
                int d = f4i * 4;
                float4 v = make_float4(tile[d][j], tile[d + 1][j],
                                       tile[d + 2][j], tile[d + 3][j]);
                __stwt(&out[orow + f4i], v);
            }
        }
        __syncthreads();
    }
}

extern "C" void kernel_launch(void* const* d_in, const int* in_sizes, int n_in,
                              void* d_out, int out_size)
{
    const int*   x = (const int*)  d_in[0];
    const float* W = (const float*)d_in[1];
    float4*      o = (float4*)     d_out;

    k_zero<<<(NBUCKETS + 255) / 256, 256>>>();
    k_bin <<<(NTOK     + 255) / 256, 256>>>(x);

    dim3 grid(NBUCKETS, DIMS / DIM_CHUNK);     // (786, 4)
    k_gather<<<grid, 256>>>(W, o);
}

// round 5
// speedup vs baseline: 1.4038x; 1.0086x over previous
#include <cuda_runtime.h>
#include <cstdint>

// Embedding gather, bucket-clustered, self-resetting (2 kernels only):
//   x : [16384] int32 token ids        (d_in[0])
//   W : [1024, 50257] f32 row-major    (d_in[1]); embedding of tok = column tok
//   out[s, :] = W[:, x[s]]
//
// k_bin    : bucket tokens by tok>>6 (786 buckets, 256B window = 8 sectors)
// k_gather : block = (bucket, 128-dim chunk). Warp lanes = bucket entries,
//            each warp LDG touches <= 8 sectors. smem transpose -> coalesced
//            float4 streaming stores. Last chunk-block per bucket resets the
//            bucket counter, so no separate zeroing kernel is needed
//            (counters are zero at module load and restored every call).

#define TOKENS    50257
#define DIMS      1024
#define NTOK      16384
#define BSHIFT    6
#define NBUCKETS  ((TOKENS + 63) / 64)   // 786
#define CAP       256                    // mean fill ~20.8
#define DIM_CHUNK 128
#define NCHUNKS   (DIMS / DIM_CHUNK)     // 8

__device__ int  g_cnt[NBUCKETS];            // zero-init; self-reset each call
__device__ int  g_done[NBUCKETS];           // arrival counters; self-reset
__device__ int2 g_items[NBUCKETS * CAP];    // (tok, original position)

__global__ void k_bin(const int* __restrict__ x)
{
    int i = blockIdx.x * blockDim.x + threadIdx.x;
    if (i < NTOK) {
        int tok = __ldg(&x[i]);
        int b   = tok >> BSHIFT;
        int s   = atomicAdd(&g_cnt[b], 1);
        if (s < CAP) g_items[b * CAP + s] = make_int2(tok, i);
    }
}

// grid (786, 8), 128 threads = 4 warps x 32 dims.
__global__ __launch_bounds__(128, 12)
void k_gather(const float* __restrict__ W, float4* __restrict__ out)
{
    __shared__ float tile[DIM_CHUNK][34];   // pad 34: conflict-free both phases
    __shared__ int s_tok[32], s_pos[32];
    __shared__ int s_n;

    const int b   = blockIdx.x;
    const int tid = threadIdx.x;
    if (tid == 0) s_n = min(g_cnt[b], CAP);
    __syncthreads();
    const int n = s_n;

    const int lane = tid & 31;
    const int wd   = (tid >> 5) * 32;       // warp's dim base within chunk
    const size_t dim_base = (size_t)(blockIdx.y * DIM_CHUNK + wd) * TOKENS;

    for (int t0 = 0; t0 < n; t0 += 32) {
        const int m = min(32, n - t0);

        if (tid < m) {
            int2 e = g_items[b * CAP + t0 + tid];
            s_tok[tid] = e.x;
            s_pos[tid] = e.y;
        }
        __syncthreads();

        // Phase 1: lanes = clustered tokens (<=256B span -> <=8 sectors),
        // 32 independent strided loads per thread (high MLP).
        if (lane < m) {
            const float* base = W + dim_base + s_tok[lane];
#pragma unroll
            for (int k = 0; k < 32; k++)
                tile[wd + k][lane] = __ldg(base + (size_t)k * TOKENS);
        }
        __syncthreads();

        // Phase 2: streaming float4 stores; j = token slot, 8 f4/thread.
        const int j  = tid >> 2;
        const int f0 = tid & 3;
        if (j < m) {
            const size_t orow = (size_t)s_pos[j] * (DIMS / 4)
                              + blockIdx.y * (DIM_CHUNK / 4);
#pragma unroll
            for (int k = 0; k < 8; k++) {
                int f4i = f0 + k * 4;
                int d = f4i * 4;
                float4 v = make_float4(tile[d][j], tile[d + 1][j],
                                       tile[d + 2][j], tile[d + 3][j]);
                __stwt(&out[orow + f4i], v);
            }
        }
        __syncthreads();
    }

    // Self-reset: last chunk-block for this bucket restores counters to 0.
    // Every block read g_cnt[b] before its arrival, so the reset can't be
    // observed early; kernel boundary orders it before the next k_bin.
    if (tid == 0) {
        int v = atomicAdd(&g_done[b], 1);
        if (v == NCHUNKS - 1) {
            g_cnt[b]  = 0;
            g_done[b] = 0;
        }
    }
}

extern "C" void kernel_launch(void* const* d_in, const int* in_sizes, int n_in,
                              void* d_out, int out_size)
{
    const int*   x = (const int*)  d_in[0];
    const float* W = (const float*)d_in[1];
    float4*      o = (float4*)     d_out;

    k_bin<<<(NTOK + 255) / 256, 256>>>(x);

    dim3 grid(NBUCKETS, NCHUNKS);            // (786, 8)
    k_gather<<<grid, 128>>>(W, o);
}